// round 11
// baseline (speedup 1.0000x reference)
#include <cuda_runtime.h>
#include <cuda_bf16.h>
#include <stdint.h>

#define N_ROWS   131072
#define C_DIM    64
#define K_CODES  4096
#define M_TILE   128
#define N_TILE   128
#define THREADS  256
#define DELTA    0.015625f    // screen margin >> 2x worst-case bf16-3term error

// Output layout: [quantized N*C][idx N][residual_quantized N*C][idx_r N]
#define OFF_Q     ((size_t)0)
#define OFF_IDX   ((size_t)N_ROWS * C_DIM)
#define OFF_RQ    ((size_t)N_ROWS * C_DIM + N_ROWS)
#define OFF_IDXR  ((size_t)2 * N_ROWS * C_DIM + N_ROWS)

// GMEM images: bf16 hi/lo split of (-2*codebook), packed per 128-code tile in
// the exact SMEM fragment layout (32KB/tile) so cp.async copies are linear.
__device__ float g_imgMain[32 * 8192];
__device__ float g_imgRes [32 * 8192];
__device__ float g_csq[K_CODES];
__device__ float g_rsq[K_CODES];

// ---- SMEM float-index map ----
#define SA       0                    // A tile: 128 rows x 256B = 32KB
#define SB(b)    (8192 + (b) * 8192)  // B buffers: 32KB each
#define SCSQ(b)  (24576 + (b) * 128)
#define SRI      24832
#define SMEM_FLOATS 24992             // 99968 bytes -> 2 CTAs/SM

// Byte offset of the fragment-packed cell (r, kchunk, ka) within a tile.
// Cell = 16B: [hi(2ka..2ka+1) | hi(2ka+8..+9) | lo(2ka..) | lo(2ka+8..)],
// bf16 pairs packed little-endian. Parity-XOR on the 64B kc-block makes the
// warp's LDS.128 pattern (8 distinct r-or-n, 4 ka) bank-conflict-free.
__device__ __forceinline__ int cell_byte(int r, int kc, int ka) {
    return r * 256 + ((kc ^ (r & 1)) << 6) + ka * 16;
}

__device__ __forceinline__ uint32_t bf16pair(float v0, float v1) {
    __nv_bfloat162 p = __floats2bfloat162_rn(v0, v1);
    return *(uint32_t*)&p;
}

// ---- Prep: pack bf16-split images + squared norms (one thread per code) ----
__global__ void prep_kernel(const float* __restrict__ cb,
                            const float* __restrict__ rcb) {
    int n = blockIdx.x * blockDim.x + threadIdx.x;
    if (n >= K_CODES) return;
    int t = n >> 7, r = n & 127;
#pragma unroll
    for (int img = 0; img < 2; img++) {
        const float* src = img ? rcb : cb;
        char* dst = (char*)(img ? g_imgRes : g_imgMain) + (size_t)t * 32768;
        float s = 0.f;
        for (int k = 0; k < C_DIM; k += 2) {
            float v0 = src[(size_t)n * C_DIM + k];
            float v1 = src[(size_t)n * C_DIM + k + 1];
            s = fmaf(v0, v0, fmaf(v1, v1, s));
            float w0 = -2.f * v0, w1 = -2.f * v1;
            float h0 = __bfloat162float(__float2bfloat16(w0));
            float h1 = __bfloat162float(__float2bfloat16(w1));
            int kc = k >> 4, kk = k & 15, sh = kk >> 3, ka = (kk >> 1) & 3;
            int base = cell_byte(r, kc, ka) + sh * 4;
            *(uint32_t*)(dst + base)     = bf16pair(h0, h1);
            *(uint32_t*)(dst + base + 8) = bf16pair(w0 - h0, w1 - h1);
        }
        if (img) g_rsq[n] = s; else g_csq[n] = s;
    }
}

__device__ __forceinline__ void cpasync16(uint32_t dst, const float* src) {
    asm volatile("cp.async.cg.shared.global [%0], [%1], 16;"
                 :: "r"(dst), "l"(src) : "memory");
}

__device__ __forceinline__ void mma_bf16(float* d,
                                         uint32_t a0, uint32_t a1, uint32_t a2, uint32_t a3,
                                         uint32_t b0, uint32_t b1) {
    asm volatile(
        "mma.sync.aligned.m16n8k16.row.col.f32.bf16.bf16.f32 "
        "{%0,%1,%2,%3}, {%4,%5,%6,%7}, {%8,%9}, {%0,%1,%2,%3};"
        : "+f"(d[0]), "+f"(d[1]), "+f"(d[2]), "+f"(d[3])
        : "r"(a0), "r"(a1), "r"(a2), "r"(a3), "r"(b0), "r"(b1));
}

// ---- Exact fp32 rescore (rare; L2-hot) ----
__device__ __noinline__ float exact_score(const float* __restrict__ xrow,
                                          const float* __restrict__ qrow,
                                          const float* __restrict__ crow,
                                          float csq)
{
    float d0 = 0.f, d1 = 0.f, d2 = 0.f, d3 = 0.f;
#pragma unroll
    for (int j = 0; j < 16; j++) {
        float4 xv = __ldg((const float4*)xrow + j);
        float4 cv = __ldg((const float4*)crow + j);
        if (qrow) {
            float4 qv = __ldg((const float4*)qrow + j);
            xv.x -= qv.x; xv.y -= qv.y; xv.z -= qv.z; xv.w -= qv.w;
        }
        d0 = fmaf(xv.x, cv.x, d0);
        d1 = fmaf(xv.y, cv.y, d1);
        d2 = fmaf(xv.z, cv.z, d2);
        d3 = fmaf(xv.w, cv.w, d3);
    }
    return fmaf(-2.f, (d0 + d1) + (d2 + d3), csq);
}

// cp.async one packed code tile + csq into buffer buf.
__device__ __forceinline__ void copy_tile(int u, int buf, int tid, uint32_t sb) {
    const float* src = (u < 32 ? g_imgMain : g_imgRes) + (size_t)(u & 31) * 8192;
    uint32_t d = sb + SB(buf) * 4;
#pragma unroll
    for (int o = 0; o < 8; o++) {
        int i = tid + o * 256;
        cpasync16(d + i * 16, src + i * 4);
    }
    if (tid < 32) {
        const float* sq = (u < 32 ? g_csq : g_rsq) + (u & 31) * 128;
        cpasync16(sb + SCSQ(buf) * 4 + tid * 16, sq + tid * 4);
    }
    asm volatile("cp.async.commit_group;" ::: "memory");
}

// Build/refresh one A row (bf16 split of x or residual) into the A tile.
__device__ __forceinline__ void build_row(float* smem, int r,
                                          const float* __restrict__ xrow,
                                          const float* __restrict__ qrow) {
    char* A = (char*)smem;   // SA == 0
#pragma unroll
    for (int j = 0; j < 16; j++) {
        float4 v = ((const float4*)xrow)[j];
        if (qrow) {
            float4 q = ((const float4*)qrow)[j];
            v.x -= q.x; v.y -= q.y; v.z -= q.z; v.w -= q.w;
        }
        float va[4] = {v.x, v.y, v.z, v.w};
#pragma unroll
        for (int p = 0; p < 2; p++) {
            int k = j * 4 + p * 2;
            float w0 = va[p * 2], w1 = va[p * 2 + 1];
            float h0 = __bfloat162float(__float2bfloat16(w0));
            float h1 = __bfloat162float(__float2bfloat16(w1));
            int kc = k >> 4, kk = k & 15, sh = kk >> 3, ka = (kk >> 1) & 3;
            int base = cell_byte(r, kc, ka) + sh * 4;
            *(uint32_t*)(A + base)     = bf16pair(h0, h1);
            *(uint32_t*)(A + base + 8) = bf16pair(w0 - h0, w1 - h1);
        }
    }
}

// Stage end: quad-reduce exact argmin, gather/emit outputs, rebuild A (stage 0).
__device__ __forceinline__ void finalize_stage(
    int stage, int row0, int tid, int w, int lane,
    float* smem, const float* __restrict__ cbraw, const float* __restrict__ x,
    float* __restrict__ out,
    float& bel, int& iel, float& beh, int& ieh, float& bl, float& bh)
{
#pragma unroll
    for (int off = 1; off < 4; off <<= 1) {
        float so = __shfl_xor_sync(0xffffffffu, bel, off);
        int   bo = __shfl_xor_sync(0xffffffffu, iel, off);
        if (so < bel || (so == bel && bo < iel)) { bel = so; iel = bo; }
        so = __shfl_xor_sync(0xffffffffu, beh, off);
        bo = __shfl_xor_sync(0xffffffffu, ieh, off);
        if (so < beh || (so == beh && bo < ieh)) { beh = so; ieh = bo; }
    }
    if ((lane & 3) == 0) {
        int r = w * 16 + (lane >> 2);
        ((int*)smem)[SRI + r]     = iel;
        ((int*)smem)[SRI + r + 8] = ieh;
    }
    __syncthreads();
    if (tid < 128) {
        int r = tid;
        int code = ((int*)smem)[SRI + r];
        const float* qrow = cbraw + (size_t)code * C_DIM;
        float* oq = out + (stage ? OFF_RQ : OFF_Q) + (size_t)(row0 + r) * C_DIM;
#pragma unroll
        for (int j = 0; j < 16; j++)
            *(float4*)(oq + j * 4) = ((const float4*)qrow)[j];
        if (stage == 0)
            build_row(smem, r, x + (size_t)(row0 + r) * C_DIM, qrow);
        out[(stage ? OFF_IDXR : OFF_IDX) + row0 + r] = (float)code;
    }
    bel = beh = 3.402823466e38f; iel = ieh = 0;
    bl  = bh  = 3.402823466e38f;
    __syncthreads();
}

__global__ __launch_bounds__(THREADS, 2)
void rq7_kernel(const float* __restrict__ x,
                const float* __restrict__ cb,
                const float* __restrict__ rcb,
                float* __restrict__ out)
{
    extern __shared__ float smem[];
    const uint32_t sb = (uint32_t)__cvta_generic_to_shared(smem);
    const int tid = threadIdx.x, w = tid >> 5, lane = tid & 31;
    const int row0 = blockIdx.x * M_TILE;

    copy_tile(0, 0, tid, sb);
    copy_tile(1, 1, tid, sb);

    if (tid < 128)
        build_row(smem, tid, x + (size_t)(row0 + tid) * C_DIM, (const float*)0);

    float bl = 3.402823466e38f, bh = 3.402823466e38f;     // approx screens
    float bel = 3.402823466e38f, beh = 3.402823466e38f;   // exact bests
    int   iel = 0, ieh = 0;

    const int ra = w * 16 + (lane >> 2);
    const int ka = lane & 3;
    const int q  = lane >> 2;
    // A cell bases (parity of ra and ra+8 identical)
    const int abase = ra * 256 + ka * 16;
    const int apar  = ra & 1;
    // B cell base within a buffer (n = nb*8 + q; parity = q&1, nb-independent)
    const int bblk  = q * 256 + ka * 16;
    const int bpar  = q & 1;
    const float *qrow_l = 0, *qrow_h = 0;

    for (int tt = 0; tt < 64; tt++) {
        if (tt < 63) asm volatile("cp.async.wait_group 1;" ::: "memory");
        else         asm volatile("cp.async.wait_group 0;" ::: "memory");
        __syncthreads();

        const int buf = tt & 1;
        const int stage = tt >> 5;
        const char* A = (const char*)smem;
        const char* B = (const char*)smem + SB(buf) * 4;

        float acc[16][4];
#pragma unroll
        for (int nb = 0; nb < 16; nb++)
#pragma unroll
            for (int j = 0; j < 4; j++) acc[nb][j] = 0.f;

#pragma unroll
        for (int kc = 0; kc < 4; kc++) {
            const int ablk = ((kc ^ apar) << 6);
            float4 fa = *(const float4*)(A + abase + ablk);
            float4 fb = *(const float4*)(A + abase + 2048 + ablk);
            uint32_t ah0 = __float_as_uint(fa.x), ah2 = __float_as_uint(fa.y);
            uint32_t al0 = __float_as_uint(fa.z), al2 = __float_as_uint(fa.w);
            uint32_t ah1 = __float_as_uint(fb.x), ah3 = __float_as_uint(fb.y);
            uint32_t al1 = __float_as_uint(fb.z), al3 = __float_as_uint(fb.w);
            const char* Bk = B + bblk + ((kc ^ bpar) << 6);
#pragma unroll
            for (int g = 0; g < 4; g++) {          // groups of 4 n-blocks
                uint32_t bhv[4][2], blv[4][2];
#pragma unroll
                for (int nn = 0; nn < 4; nn++) {
                    float4 f = *(const float4*)(Bk + (g * 4 + nn) * 2048);
                    bhv[nn][0] = __float_as_uint(f.x); bhv[nn][1] = __float_as_uint(f.y);
                    blv[nn][0] = __float_as_uint(f.z); blv[nn][1] = __float_as_uint(f.w);
                }
#pragma unroll
                for (int nn = 0; nn < 4; nn++)     // hi * hi
                    mma_bf16(acc[g * 4 + nn], ah0, ah1, ah2, ah3, bhv[nn][0], bhv[nn][1]);
#pragma unroll
                for (int nn = 0; nn < 4; nn++)     // hi * lo
                    mma_bf16(acc[g * 4 + nn], ah0, ah1, ah2, ah3, blv[nn][0], blv[nn][1]);
#pragma unroll
                for (int nn = 0; nn < 4; nn++)     // lo * hi
                    mma_bf16(acc[g * 4 + nn], al0, al1, al2, al3, bhv[nn][0], bhv[nn][1]);
            }
        }

        // ---- Pass 1: +csq, tile minima ----
        const float* cs = smem + SCSQ(buf);
        const int cbase = (tt & 31) * 128;
        float tl = 3.402823466e38f, th = 3.402823466e38f;
#pragma unroll
        for (int nb = 0; nb < 16; nb++) {
            float2 c2 = *(const float2*)(cs + nb * 8 + ka * 2);
            acc[nb][0] += c2.x; acc[nb][1] += c2.y;
            acc[nb][2] += c2.x; acc[nb][3] += c2.y;
            tl = fminf(tl, fminf(acc[nb][0], acc[nb][1]));
            th = fminf(th, fminf(acc[nb][2], acc[nb][3]));
        }
        bl = fminf(bl, tl);
        bh = fminf(bh, th);
        const float thr_l = bl + DELTA, thr_h = bh + DELTA;

        // ---- Pass 2: screen + inline exact rescore ----
        const float* xrl = x + (size_t)(row0 + ra) * C_DIM;
        const float* xrh = xrl + 8 * C_DIM;
        const float* cbs = stage ? rcb : cb;
        const float* sqs = stage ? g_rsq : g_csq;
        const float* ql  = stage ? qrow_l : (const float*)0;
        const float* qh  = stage ? qrow_h : (const float*)0;
#pragma unroll
        for (int nb = 0; nb < 16; nb++) {
            const int g = cbase + nb * 8 + ka * 2;
            if (acc[nb][0] < thr_l) {
                float e = exact_score(xrl, ql, cbs + (size_t)g * C_DIM, __ldg(sqs + g));
                if (e < bel) { bel = e; iel = g; }
            }
            if (acc[nb][1] < thr_l) {
                float e = exact_score(xrl, ql, cbs + (size_t)(g + 1) * C_DIM, __ldg(sqs + g + 1));
                if (e < bel) { bel = e; iel = g + 1; }
            }
            if (acc[nb][2] < thr_h) {
                float e = exact_score(xrh, qh, cbs + (size_t)g * C_DIM, __ldg(sqs + g));
                if (e < beh) { beh = e; ieh = g; }
            }
            if (acc[nb][3] < thr_h) {
                float e = exact_score(xrh, qh, cbs + (size_t)(g + 1) * C_DIM, __ldg(sqs + g + 1));
                if (e < beh) { beh = e; ieh = g + 1; }
            }
        }
        __syncthreads();

        if (tt == 31) {
            finalize_stage(0, row0, tid, w, lane, smem, cb, x, out,
                           bel, iel, beh, ieh, bl, bh);
            int c0l = ((int*)smem)[SRI + ra];
            int c0h = ((int*)smem)[SRI + ra + 8];
            qrow_l = cb + (size_t)c0l * C_DIM;
            qrow_h = cb + (size_t)c0h * C_DIM;
        }

        if (tt + 2 < 64) copy_tile(tt + 2, buf, tid, sb);
    }

    finalize_stage(1, row0, tid, w, lane, smem, rcb, x, out,
                   bel, iel, beh, ieh, bl, bh);
}

extern "C" void kernel_launch(void* const* d_in, const int* in_sizes, int n_in,
                              void* d_out, int out_size) {
    const float* x   = (const float*)d_in[0];
    const float* cb  = (const float*)d_in[1];
    const float* rcb = (const float*)d_in[2];
    float* out = (float*)d_out;

    static int smem_set = 0;
    if (!smem_set) {
        cudaFuncSetAttribute(rq7_kernel,
                             cudaFuncAttributeMaxDynamicSharedMemorySize,
                             SMEM_FLOATS * sizeof(float));
        smem_set = 1;
    }

    prep_kernel<<<K_CODES / 256, 256>>>(cb, rcb);
    rq7_kernel<<<N_ROWS / M_TILE, THREADS, SMEM_FLOATS * sizeof(float)>>>(x, cb, rcb, out);
}

// round 13
// speedup vs baseline: 2.9344x; 2.9344x over previous
#include <cuda_runtime.h>
#include <cuda_bf16.h>
#include <stdint.h>

#define N_ROWS   131072
#define C_DIM    64
#define K_CODES  4096
#define M_TILE   128
#define THREADS  256
#define DELTA    0.015625f    // screen margin >> worst-case bf16-3term error

// Output layout: [quantized N*C][idx N][residual_quantized N*C][idx_r N]
#define OFF_Q     ((size_t)0)
#define OFF_IDX   ((size_t)N_ROWS * C_DIM)
#define OFF_RQ    ((size_t)N_ROWS * C_DIM + N_ROWS)
#define OFF_IDXR  ((size_t)2 * N_ROWS * C_DIM + N_ROWS)

// GMEM images: bf16 hi/lo split of (-2*codebook), packed per 128-code tile in
// the exact SMEM fragment layout (32KB/tile) so cp.async copies are linear.
__device__ float g_imgMain[32 * 8192];
__device__ float g_imgRes [32 * 8192];
__device__ float g_csq[K_CODES];
__device__ float g_rsq[K_CODES];

// ---- SMEM float-index map ----
#define SA       0                    // A tile: 128 rows x 256B = 32KB
#define SB(b)    (8192 + (b) * 8192)  // B buffers: 32KB each
#define SCSQ(b)  (24576 + (b) * 128)
#define SRI      24832
#define SMEM_FLOATS 24992             // 99968 bytes -> 2 CTAs/SM

// Byte offset of the fragment-packed cell (r, kchunk, ka) within a tile.
// Cell = 16B: [hi(2ka..2ka+1) | hi(2ka+8..+9) | lo(2ka..) | lo(2ka+8..)].
// Parity-XOR on the 64B kc-block keeps the warp LDS.128 pattern conflict-free.
__device__ __forceinline__ int cell_byte(int r, int kc, int ka) {
    return r * 256 + ((kc ^ (r & 1)) << 6) + ka * 16;
}

__device__ __forceinline__ uint32_t bf16pair(float v0, float v1) {
    __nv_bfloat162 p = __floats2bfloat162_rn(v0, v1);
    return *(uint32_t*)&p;
}

// ---- Prep: pack bf16-split images + squared norms (one thread per code) ----
__global__ void prep_kernel(const float* __restrict__ cb,
                            const float* __restrict__ rcb) {
    int n = blockIdx.x * blockDim.x + threadIdx.x;
    if (n >= K_CODES) return;
    int t = n >> 7, r = n & 127;
#pragma unroll
    for (int img = 0; img < 2; img++) {
        const float* src = img ? rcb : cb;
        char* dst = (char*)(img ? g_imgRes : g_imgMain) + (size_t)t * 32768;
        float s = 0.f;
        for (int k = 0; k < C_DIM; k += 2) {
            float v0 = src[(size_t)n * C_DIM + k];
            float v1 = src[(size_t)n * C_DIM + k + 1];
            s = fmaf(v0, v0, fmaf(v1, v1, s));
            float w0 = -2.f * v0, w1 = -2.f * v1;
            float h0 = __bfloat162float(__float2bfloat16(w0));
            float h1 = __bfloat162float(__float2bfloat16(w1));
            int kc = k >> 4, kk = k & 15, sh = kk >> 3, ka = (kk >> 1) & 3;
            int base = cell_byte(r, kc, ka) + sh * 4;
            *(uint32_t*)(dst + base)     = bf16pair(h0, h1);
            *(uint32_t*)(dst + base + 8) = bf16pair(w0 - h0, w1 - h1);
        }
        if (img) g_rsq[n] = s; else g_csq[n] = s;
    }
}

__device__ __forceinline__ void cpasync16(uint32_t dst, const float* src) {
    asm volatile("cp.async.cg.shared.global [%0], [%1], 16;"
                 :: "r"(dst), "l"(src) : "memory");
}

__device__ __forceinline__ void mma_bf16(float* d,
                                         uint32_t a0, uint32_t a1, uint32_t a2, uint32_t a3,
                                         uint32_t b0, uint32_t b1) {
    asm volatile(
        "mma.sync.aligned.m16n8k16.row.col.f32.bf16.bf16.f32 "
        "{%0,%1,%2,%3}, {%4,%5,%6,%7}, {%8,%9}, {%0,%1,%2,%3};"
        : "+f"(d[0]), "+f"(d[1]), "+f"(d[2]), "+f"(d[3])
        : "r"(a0), "r"(a1), "r"(a2), "r"(a3), "r"(b0), "r"(b1));
}

// ---- Exact fp32 rescore (rare path; called only with accumulators dead) ----
__device__ __noinline__ float exact_score(const float* __restrict__ xrow,
                                          const float* __restrict__ qrow,
                                          const float* __restrict__ crow,
                                          float csq)
{
    float d0 = 0.f, d1 = 0.f, d2 = 0.f, d3 = 0.f;
#pragma unroll
    for (int j = 0; j < 16; j++) {
        float4 xv = __ldg((const float4*)xrow + j);
        float4 cv = __ldg((const float4*)crow + j);
        if (qrow) {
            float4 qv = __ldg((const float4*)qrow + j);
            xv.x -= qv.x; xv.y -= qv.y; xv.z -= qv.z; xv.w -= qv.w;
        }
        d0 = fmaf(xv.x, cv.x, d0);
        d1 = fmaf(xv.y, cv.y, d1);
        d2 = fmaf(xv.z, cv.z, d2);
        d3 = fmaf(xv.w, cv.w, d3);
    }
    return fmaf(-2.f, (d0 + d1) + (d2 + d3), csq);
}

struct RescoreCtx {
    const float *xrl, *xrh, *ql, *qh, *cbs, *sqs;
};

__device__ __noinline__ void rescore_one(unsigned v, const RescoreCtx& c,
                                         float& bel, int& iel,
                                         float& beh, int& ieh)
{
    int code = (int)(v >> 1);
    const float* xrow = (v & 1) ? c.xrh : c.xrl;
    const float* qrow = (v & 1) ? c.qh : c.ql;
    float e = exact_score(xrow, qrow, c.cbs + (size_t)code * C_DIM,
                          __ldg(c.sqs + code));
    if (v & 1) { if (e < beh) { beh = e; ieh = code; } }
    else       { if (e < bel) { bel = e; iel = code; } }
}

// cp.async one packed code tile + csq into buffer buf.
__device__ __forceinline__ void copy_tile(int u, int buf, int tid, uint32_t sb) {
    const float* src = (u < 32 ? g_imgMain : g_imgRes) + (size_t)(u & 31) * 8192;
    uint32_t d = sb + SB(buf) * 4;
#pragma unroll
    for (int o = 0; o < 8; o++) {
        int i = tid + o * 256;
        cpasync16(d + i * 16, src + i * 4);
    }
    if (tid < 32) {
        const float* sq = (u < 32 ? g_csq : g_rsq) + (u & 31) * 128;
        cpasync16(sb + SCSQ(buf) * 4 + tid * 16, sq + tid * 4);
    }
    asm volatile("cp.async.commit_group;" ::: "memory");
}

// Build/refresh one A row (bf16 split of x or residual) into the A tile.
__device__ __forceinline__ void build_row(float* smem, int r,
                                          const float* __restrict__ xrow,
                                          const float* __restrict__ qrow) {
    char* A = (char*)smem;   // SA == 0
#pragma unroll
    for (int j = 0; j < 16; j++) {
        float4 v = ((const float4*)xrow)[j];
        if (qrow) {
            float4 q = ((const float4*)qrow)[j];
            v.x -= q.x; v.y -= q.y; v.z -= q.z; v.w -= q.w;
        }
        float va[4] = {v.x, v.y, v.z, v.w};
#pragma unroll
        for (int p = 0; p < 2; p++) {
            int k = j * 4 + p * 2;
            float w0 = va[p * 2], w1 = va[p * 2 + 1];
            float h0 = __bfloat162float(__float2bfloat16(w0));
            float h1 = __bfloat162float(__float2bfloat16(w1));
            int kc = k >> 4, kk = k & 15, sh = kk >> 3, ka = (kk >> 1) & 3;
            int base = cell_byte(r, kc, ka) + sh * 4;
            *(uint32_t*)(A + base)     = bf16pair(h0, h1);
            *(uint32_t*)(A + base + 8) = bf16pair(w0 - h0, w1 - h1);
        }
    }
}

// Stage end: quad-reduce exact argmin, gather/emit outputs, rebuild A (stage 0).
__device__ __forceinline__ void finalize_stage(
    int stage, int row0, int tid, int w, int lane,
    float* smem, const float* __restrict__ cbraw, const float* __restrict__ x,
    float* __restrict__ out,
    float& bel, int& iel, float& beh, int& ieh, float& bl, float& bh)
{
#pragma unroll
    for (int off = 1; off < 4; off <<= 1) {
        float so = __shfl_xor_sync(0xffffffffu, bel, off);
        int   bo = __shfl_xor_sync(0xffffffffu, iel, off);
        if (so < bel || (so == bel && bo < iel)) { bel = so; iel = bo; }
        so = __shfl_xor_sync(0xffffffffu, beh, off);
        bo = __shfl_xor_sync(0xffffffffu, ieh, off);
        if (so < beh || (so == beh && bo < ieh)) { beh = so; ieh = bo; }
    }
    if ((lane & 3) == 0) {
        int r = w * 16 + (lane >> 2);
        ((int*)smem)[SRI + r]     = iel;
        ((int*)smem)[SRI + r + 8] = ieh;
    }
    __syncthreads();
    if (tid < 128) {
        int r = tid;
        int code = ((int*)smem)[SRI + r];
        const float* qrow = cbraw + (size_t)code * C_DIM;
        float* oq = out + (stage ? OFF_RQ : OFF_Q) + (size_t)(row0 + r) * C_DIM;
#pragma unroll
        for (int j = 0; j < 16; j++)
            *(float4*)(oq + j * 4) = ((const float4*)qrow)[j];
        if (stage == 0)
            build_row(smem, r, x + (size_t)(row0 + r) * C_DIM, qrow);
        out[(stage ? OFF_IDXR : OFF_IDX) + row0 + r] = (float)code;
    }
    bel = beh = 3.402823466e38f; iel = ieh = 0;
    bl  = bh  = 3.402823466e38f;
    __syncthreads();
}

__global__ __launch_bounds__(THREADS, 2)
void rq8_kernel(const float* __restrict__ x,
                const float* __restrict__ cb,
                const float* __restrict__ rcb,
                float* __restrict__ out)
{
    extern __shared__ float smem[];
    const uint32_t sb = (uint32_t)__cvta_generic_to_shared(smem);
    const int tid = threadIdx.x, w = tid >> 5, lane = tid & 31;
    const int row0 = blockIdx.x * M_TILE;

    copy_tile(0, 0, tid, sb);
    copy_tile(1, 1, tid, sb);

    if (tid < 128)
        build_row(smem, tid, x + (size_t)(row0 + tid) * C_DIM, (const float*)0);

    float bl = 3.402823466e38f, bh = 3.402823466e38f;     // approx screens
    float bel = 3.402823466e38f, beh = 3.402823466e38f;   // exact bests
    int   iel = 0, ieh = 0;

    const int ra = w * 16 + (lane >> 2);
    const int ka = lane & 3;
    const int q  = lane >> 2;
    const int abase = ra * 256 + ka * 16;   // A cell base (ra, ra+8 same parity)
    const int apar  = ra & 1;
    const int bblk  = q * 256 + ka * 16;    // B cell base within an n-block
    const int bpar  = q & 1;
    const float *qrow_l = 0, *qrow_h = 0;

    for (int tt = 0; tt < 64; tt++) {
        if (tt < 63) asm volatile("cp.async.wait_group 1;" ::: "memory");
        else         asm volatile("cp.async.wait_group 0;" ::: "memory");
        __syncthreads();

        const int buf = tt & 1;
        const int stage = tt >> 5;
        const char* A = (const char*)smem;
        const char* B = (const char*)smem + SB(buf) * 4;
        const int cbase = (tt & 31) * 128;

        RescoreCtx ctx;
        ctx.xrl = x + (size_t)(row0 + ra) * C_DIM;
        ctx.xrh = ctx.xrl + 8 * C_DIM;
        ctx.ql  = stage ? qrow_l : (const float*)0;
        ctx.qh  = stage ? qrow_h : (const float*)0;
        ctx.cbs = stage ? rcb : cb;
        ctx.sqs = stage ? g_rsq : g_csq;

#pragma unroll
        for (int pass = 0; pass < 2; pass++) {
            const char* Bp = B + pass * 16384;      // n-blocks 8..15 at +16KB

            float acc[8][4];
#pragma unroll
            for (int nb = 0; nb < 8; nb++)
#pragma unroll
                for (int j = 0; j < 4; j++) acc[nb][j] = 0.f;

#pragma unroll
            for (int kc = 0; kc < 4; kc++) {
                const int ablk = ((kc ^ apar) << 6);
                float4 fa = *(const float4*)(A + abase + ablk);
                float4 fb = *(const float4*)(A + abase + 2048 + ablk);
                uint32_t ah0 = __float_as_uint(fa.x), ah2 = __float_as_uint(fa.y);
                uint32_t al0 = __float_as_uint(fa.z), al2 = __float_as_uint(fa.w);
                uint32_t ah1 = __float_as_uint(fb.x), ah3 = __float_as_uint(fb.y);
                uint32_t al1 = __float_as_uint(fb.z), al3 = __float_as_uint(fb.w);
                const char* Bk = Bp + bblk + ((kc ^ bpar) << 6);
#pragma unroll
                for (int g = 0; g < 2; g++) {       // 2 groups of 4 n-blocks
                    uint32_t bhv[4][2], blv[4][2];
#pragma unroll
                    for (int nn = 0; nn < 4; nn++) {
                        float4 f = *(const float4*)(Bk + (g * 4 + nn) * 2048);
                        bhv[nn][0] = __float_as_uint(f.x); bhv[nn][1] = __float_as_uint(f.y);
                        blv[nn][0] = __float_as_uint(f.z); blv[nn][1] = __float_as_uint(f.w);
                    }
#pragma unroll
                    for (int nn = 0; nn < 4; nn++)  // hi * hi
                        mma_bf16(acc[g * 4 + nn], ah0, ah1, ah2, ah3, bhv[nn][0], bhv[nn][1]);
#pragma unroll
                    for (int nn = 0; nn < 4; nn++)  // hi * lo
                        mma_bf16(acc[g * 4 + nn], ah0, ah1, ah2, ah3, blv[nn][0], blv[nn][1]);
#pragma unroll
                    for (int nn = 0; nn < 4; nn++)  // lo * hi
                        mma_bf16(acc[g * 4 + nn], al0, al1, al2, al3, bhv[nn][0], bhv[nn][1]);
                }
            }

            // ---- Pass epilogue 1: +csq, running minima ----
            const float* cs = smem + SCSQ(buf) + pass * 64;
            const int cbp = cbase + pass * 64;
            float tl = 3.402823466e38f, th = 3.402823466e38f;
#pragma unroll
            for (int nb = 0; nb < 8; nb++) {
                float2 c2 = *(const float2*)(cs + nb * 8 + ka * 2);
                acc[nb][0] += c2.x; acc[nb][1] += c2.y;
                acc[nb][2] += c2.x; acc[nb][3] += c2.y;
                tl = fminf(tl, fminf(acc[nb][0], acc[nb][1]));
                th = fminf(th, fminf(acc[nb][2], acc[nb][3]));
            }
            bl = fminf(bl, tl);
            bh = fminf(bh, th);
            const float thr_l = bl + DELTA, thr_h = bh + DELTA;

            // ---- Pass epilogue 2: screen into registers (NO calls here) ----
            unsigned cand[4];
            int nc = 0;
#pragma unroll
            for (int nb = 0; nb < 8; nb++) {
                const int g = cbp + nb * 8 + ka * 2;
                if (acc[nb][0] < thr_l) { if (nc < 4) cand[nc] = (unsigned)(g << 1);           nc++; }
                if (acc[nb][1] < thr_l) { if (nc < 4) cand[nc] = (unsigned)((g + 1) << 1);     nc++; }
                if (acc[nb][2] < thr_h) { if (nc < 4) cand[nc] = (unsigned)((g << 1) | 1);     nc++; }
                if (acc[nb][3] < thr_h) { if (nc < 4) cand[nc] = (unsigned)(((g + 1) << 1) | 1); nc++; }
            }

            // ---- Deferred exact rescore: acc is dead past this point ----
            if (nc > 0) {
                if (nc <= 4) {
                    for (int i = 0; i < nc; i++)
                        rescore_one(cand[i], ctx, bel, iel, beh, ieh);
                } else {
                    // Overflow (astronomically rare): rescore the full range.
                    for (int nb = 0; nb < 8; nb++) {
                        const int g = cbp + nb * 8 + ka * 2;
                        rescore_one((unsigned)(g << 1),           ctx, bel, iel, beh, ieh);
                        rescore_one((unsigned)((g + 1) << 1),     ctx, bel, iel, beh, ieh);
                        rescore_one((unsigned)((g << 1) | 1),     ctx, bel, iel, beh, ieh);
                        rescore_one((unsigned)(((g + 1) << 1) | 1), ctx, bel, iel, beh, ieh);
                    }
                }
            }
        }
        __syncthreads();

        if (tt == 31) {
            finalize_stage(0, row0, tid, w, lane, smem, cb, x, out,
                           bel, iel, beh, ieh, bl, bh);
            int c0l = ((int*)smem)[SRI + ra];
            int c0h = ((int*)smem)[SRI + ra + 8];
            qrow_l = cb + (size_t)c0l * C_DIM;
            qrow_h = cb + (size_t)c0h * C_DIM;
        }

        if (tt + 2 < 64) copy_tile(tt + 2, buf, tid, sb);
    }

    finalize_stage(1, row0, tid, w, lane, smem, rcb, x, out,
                   bel, iel, beh, ieh, bl, bh);
}

extern "C" void kernel_launch(void* const* d_in, const int* in_sizes, int n_in,
                              void* d_out, int out_size) {
    const float* x   = (const float*)d_in[0];
    const float* cb  = (const float*)d_in[1];
    const float* rcb = (const float*)d_in[2];
    float* out = (float*)d_out;

    static int smem_set = 0;
    if (!smem_set) {
        cudaFuncSetAttribute(rq8_kernel,
                             cudaFuncAttributeMaxDynamicSharedMemorySize,
                             SMEM_FLOATS * sizeof(float));
        smem_set = 1;
    }

    prep_kernel<<<K_CODES / 256, 256>>>(cb, rcb);
    rq8_kernel<<<N_ROWS / M_TILE, THREADS, SMEM_FLOATS * sizeof(float)>>>(x, cb, rcb, out);
}

// round 14
// speedup vs baseline: 2.9382x; 1.0013x over previous
#include <cuda_runtime.h>
#include <cuda_bf16.h>
#include <stdint.h>

#define N_ROWS   131072
#define C_DIM    64
#define K_CODES  4096
#define M_TILE   128
#define THREADS  256
#define DELTA    0.015625f    // screen margin >> worst-case bf16-3term error

// Output layout: [quantized N*C][idx N][residual_quantized N*C][idx_r N]
#define OFF_Q     ((size_t)0)
#define OFF_IDX   ((size_t)N_ROWS * C_DIM)
#define OFF_RQ    ((size_t)N_ROWS * C_DIM + N_ROWS)
#define OFF_IDXR  ((size_t)2 * N_ROWS * C_DIM + N_ROWS)

// GMEM images: bf16 hi/lo split of (-2*codebook), packed per 128-code tile in
// the exact SMEM fragment layout (32KB/tile) so cp.async copies are linear.
__device__ float g_imgMain[32 * 8192];
__device__ float g_imgRes [32 * 8192];
__device__ float g_csq[K_CODES];
__device__ float g_rsq[K_CODES];

// ---- SMEM float-index map ----
#define SA       0                    // A tile: 128 rows x 256B = 32KB
#define SB(b)    (8192 + (b) * 8192)  // B buffers: 32KB each
#define SCSQ(b)  (24576 + (b) * 128)
#define SRI      24832
#define SMEM_FLOATS 24992             // 99968 bytes -> 2 CTAs/SM

// Byte offset of the fragment-packed cell (r, kchunk, ka) within a tile.
// Cell = 16B: [hi(2ka..2ka+1) | hi(2ka+8..+9) | lo(2ka..) | lo(2ka+8..)].
// Parity-XOR on the 64B kc-block keeps the warp LDS.128 pattern conflict-free.
__device__ __forceinline__ int cell_byte(int r, int kc, int ka) {
    return r * 256 + ((kc ^ (r & 1)) << 6) + ka * 16;
}

__device__ __forceinline__ uint32_t bf16pair(float v0, float v1) {
    __nv_bfloat162 p = __floats2bfloat162_rn(v0, v1);
    return *(uint32_t*)&p;
}

// ---- Prep: pack bf16-split images + squared norms (one thread per code) ----
__global__ void prep_kernel(const float* __restrict__ cb,
                            const float* __restrict__ rcb) {
    int n = blockIdx.x * blockDim.x + threadIdx.x;
    if (n >= K_CODES) return;
    int t = n >> 7, r = n & 127;
#pragma unroll
    for (int img = 0; img < 2; img++) {
        const float* src = img ? rcb : cb;
        char* dst = (char*)(img ? g_imgRes : g_imgMain) + (size_t)t * 32768;
        float s = 0.f;
        for (int k = 0; k < C_DIM; k += 2) {
            float v0 = src[(size_t)n * C_DIM + k];
            float v1 = src[(size_t)n * C_DIM + k + 1];
            s = fmaf(v0, v0, fmaf(v1, v1, s));
            float w0 = -2.f * v0, w1 = -2.f * v1;
            float h0 = __bfloat162float(__float2bfloat16(w0));
            float h1 = __bfloat162float(__float2bfloat16(w1));
            int kc = k >> 4, kk = k & 15, sh = kk >> 3, ka = (kk >> 1) & 3;
            int base = cell_byte(r, kc, ka) + sh * 4;
            *(uint32_t*)(dst + base)     = bf16pair(h0, h1);
            *(uint32_t*)(dst + base + 8) = bf16pair(w0 - h0, w1 - h1);
        }
        if (img) g_rsq[n] = s; else g_csq[n] = s;
    }
}

__device__ __forceinline__ void cpasync16(uint32_t dst, const float* src) {
    asm volatile("cp.async.cg.shared.global [%0], [%1], 16;"
                 :: "r"(dst), "l"(src) : "memory");
}

__device__ __forceinline__ void mma_bf16(float* d,
                                         uint32_t a0, uint32_t a1, uint32_t a2, uint32_t a3,
                                         uint32_t b0, uint32_t b1) {
    asm volatile(
        "mma.sync.aligned.m16n8k16.row.col.f32.bf16.bf16.f32 "
        "{%0,%1,%2,%3}, {%4,%5,%6,%7}, {%8,%9}, {%0,%1,%2,%3};"
        : "+f"(d[0]), "+f"(d[1]), "+f"(d[2]), "+f"(d[3])
        : "r"(a0), "r"(a1), "r"(a2), "r"(a3), "r"(b0), "r"(b1));
}

// ---- Exact fp32 rescore (rare path; called only with accumulators dead) ----
__device__ __noinline__ float exact_score(const float* __restrict__ xrow,
                                          const float* __restrict__ qrow,
                                          const float* __restrict__ crow,
                                          float csq)
{
    float d0 = 0.f, d1 = 0.f, d2 = 0.f, d3 = 0.f;
#pragma unroll
    for (int j = 0; j < 16; j++) {
        float4 xv = __ldg((const float4*)xrow + j);
        float4 cv = __ldg((const float4*)crow + j);
        if (qrow) {
            float4 qv = __ldg((const float4*)qrow + j);
            xv.x -= qv.x; xv.y -= qv.y; xv.z -= qv.z; xv.w -= qv.w;
        }
        d0 = fmaf(xv.x, cv.x, d0);
        d1 = fmaf(xv.y, cv.y, d1);
        d2 = fmaf(xv.z, cv.z, d2);
        d3 = fmaf(xv.w, cv.w, d3);
    }
    return fmaf(-2.f, (d0 + d1) + (d2 + d3), csq);
}

struct RescoreCtx {
    const float *xrl, *xrh, *ql, *qh, *cbs, *sqs;
};

__device__ __noinline__ void rescore_one(unsigned v, const RescoreCtx& c,
                                         float& bel, int& iel,
                                         float& beh, int& ieh)
{
    int code = (int)(v >> 1);
    const float* xrow = (v & 1) ? c.xrh : c.xrl;
    const float* qrow = (v & 1) ? c.qh : c.ql;
    float e = exact_score(xrow, qrow, c.cbs + (size_t)code * C_DIM,
                          __ldg(c.sqs + code));
    if (v & 1) { if (e < beh) { beh = e; ieh = code; } }
    else       { if (e < bel) { bel = e; iel = code; } }
}

// cp.async one packed code tile + csq into buffer buf.
__device__ __forceinline__ void copy_tile(int u, int buf, int tid, uint32_t sb) {
    const float* src = (u < 32 ? g_imgMain : g_imgRes) + (size_t)(u & 31) * 8192;
    uint32_t d = sb + SB(buf) * 4;
#pragma unroll
    for (int o = 0; o < 8; o++) {
        int i = tid + o * 256;
        cpasync16(d + i * 16, src + i * 4);
    }
    if (tid < 32) {
        const float* sq = (u < 32 ? g_csq : g_rsq) + (u & 31) * 128;
        cpasync16(sb + SCSQ(buf) * 4 + tid * 16, sq + tid * 4);
    }
    asm volatile("cp.async.commit_group;" ::: "memory");
}

// Build/refresh one A row (bf16 split of x or residual) into the A tile.
__device__ __forceinline__ void build_row(float* smem, int r,
                                          const float* __restrict__ xrow,
                                          const float* __restrict__ qrow) {
    char* A = (char*)smem;   // SA == 0
#pragma unroll
    for (int j = 0; j < 16; j++) {
        float4 v = ((const float4*)xrow)[j];
        if (qrow) {
            float4 q = ((const float4*)qrow)[j];
            v.x -= q.x; v.y -= q.y; v.z -= q.z; v.w -= q.w;
        }
        float va[4] = {v.x, v.y, v.z, v.w};
#pragma unroll
        for (int p = 0; p < 2; p++) {
            int k = j * 4 + p * 2;
            float w0 = va[p * 2], w1 = va[p * 2 + 1];
            float h0 = __bfloat162float(__float2bfloat16(w0));
            float h1 = __bfloat162float(__float2bfloat16(w1));
            int kc = k >> 4, kk = k & 15, sh = kk >> 3, ka = (kk >> 1) & 3;
            int base = cell_byte(r, kc, ka) + sh * 4;
            *(uint32_t*)(A + base)     = bf16pair(h0, h1);
            *(uint32_t*)(A + base + 8) = bf16pair(w0 - h0, w1 - h1);
        }
    }
}

// Stage end: quad-reduce exact argmin, gather/emit outputs, rebuild A (stage 0).
__device__ __forceinline__ void finalize_stage(
    int stage, int row0, int tid, int w, int lane,
    float* smem, const float* __restrict__ cbraw, const float* __restrict__ x,
    float* __restrict__ out,
    float& bel, int& iel, float& beh, int& ieh, float& bl, float& bh)
{
#pragma unroll
    for (int off = 1; off < 4; off <<= 1) {
        float so = __shfl_xor_sync(0xffffffffu, bel, off);
        int   bo = __shfl_xor_sync(0xffffffffu, iel, off);
        if (so < bel || (so == bel && bo < iel)) { bel = so; iel = bo; }
        so = __shfl_xor_sync(0xffffffffu, beh, off);
        bo = __shfl_xor_sync(0xffffffffu, ieh, off);
        if (so < beh || (so == beh && bo < ieh)) { beh = so; ieh = bo; }
    }
    if ((lane & 3) == 0) {
        int r = w * 16 + (lane >> 2);
        ((int*)smem)[SRI + r]     = iel;
        ((int*)smem)[SRI + r + 8] = ieh;
    }
    __syncthreads();
    if (tid < 128) {
        int r = tid;
        int code = ((int*)smem)[SRI + r];
        const float* qrow = cbraw + (size_t)code * C_DIM;
        float* oq = out + (stage ? OFF_RQ : OFF_Q) + (size_t)(row0 + r) * C_DIM;
#pragma unroll
        for (int j = 0; j < 16; j++)
            *(float4*)(oq + j * 4) = ((const float4*)qrow)[j];
        if (stage == 0)
            build_row(smem, r, x + (size_t)(row0 + r) * C_DIM, qrow);
        out[(stage ? OFF_IDXR : OFF_IDX) + row0 + r] = (float)code;
    }
    bel = beh = 3.402823466e38f; iel = ieh = 0;
    bl  = bh  = 3.402823466e38f;
    __syncthreads();
}

__global__ __launch_bounds__(THREADS, 2)
void rq8_kernel(const float* __restrict__ x,
                const float* __restrict__ cb,
                const float* __restrict__ rcb,
                float* __restrict__ out)
{
    extern __shared__ float smem[];
    const uint32_t sb = (uint32_t)__cvta_generic_to_shared(smem);
    const int tid = threadIdx.x, w = tid >> 5, lane = tid & 31;
    const int row0 = blockIdx.x * M_TILE;

    copy_tile(0, 0, tid, sb);
    copy_tile(1, 1, tid, sb);

    if (tid < 128)
        build_row(smem, tid, x + (size_t)(row0 + tid) * C_DIM, (const float*)0);

    float bl = 3.402823466e38f, bh = 3.402823466e38f;     // approx screens
    float bel = 3.402823466e38f, beh = 3.402823466e38f;   // exact bests
    int   iel = 0, ieh = 0;

    const int ra = w * 16 + (lane >> 2);
    const int ka = lane & 3;
    const int q  = lane >> 2;
    const int abase = ra * 256 + ka * 16;   // A cell base (ra, ra+8 same parity)
    const int apar  = ra & 1;
    const int bblk  = q * 256 + ka * 16;    // B cell base within an n-block
    const int bpar  = q & 1;
    const float *qrow_l = 0, *qrow_h = 0;

    for (int tt = 0; tt < 64; tt++) {
        if (tt < 63) asm volatile("cp.async.wait_group 1;" ::: "memory");
        else         asm volatile("cp.async.wait_group 0;" ::: "memory");
        __syncthreads();

        const int buf = tt & 1;
        const int stage = tt >> 5;
        const char* A = (const char*)smem;
        const char* B = (const char*)smem + SB(buf) * 4;
        const int cbase = (tt & 31) * 128;

        RescoreCtx ctx;
        ctx.xrl = x + (size_t)(row0 + ra) * C_DIM;
        ctx.xrh = ctx.xrl + 8 * C_DIM;
        ctx.ql  = stage ? qrow_l : (const float*)0;
        ctx.qh  = stage ? qrow_h : (const float*)0;
        ctx.cbs = stage ? rcb : cb;
        ctx.sqs = stage ? g_rsq : g_csq;

#pragma unroll
        for (int pass = 0; pass < 2; pass++) {
            const char* Bp = B + pass * 16384;      // n-blocks 8..15 at +16KB

            float acc[8][4];
#pragma unroll
            for (int nb = 0; nb < 8; nb++)
#pragma unroll
                for (int j = 0; j < 4; j++) acc[nb][j] = 0.f;

#pragma unroll
            for (int kc = 0; kc < 4; kc++) {
                const int ablk = ((kc ^ apar) << 6);
                float4 fa = *(const float4*)(A + abase + ablk);
                float4 fb = *(const float4*)(A + abase + 2048 + ablk);
                uint32_t ah0 = __float_as_uint(fa.x), ah2 = __float_as_uint(fa.y);
                uint32_t al0 = __float_as_uint(fa.z), al2 = __float_as_uint(fa.w);
                uint32_t ah1 = __float_as_uint(fb.x), ah3 = __float_as_uint(fb.y);
                uint32_t al1 = __float_as_uint(fb.z), al3 = __float_as_uint(fb.w);
                const char* Bk = Bp + bblk + ((kc ^ bpar) << 6);
#pragma unroll
                for (int g = 0; g < 2; g++) {       // 2 groups of 4 n-blocks
                    uint32_t bhv[4][2], blv[4][2];
#pragma unroll
                    for (int nn = 0; nn < 4; nn++) {
                        float4 f = *(const float4*)(Bk + (g * 4 + nn) * 2048);
                        bhv[nn][0] = __float_as_uint(f.x); bhv[nn][1] = __float_as_uint(f.y);
                        blv[nn][0] = __float_as_uint(f.z); blv[nn][1] = __float_as_uint(f.w);
                    }
#pragma unroll
                    for (int nn = 0; nn < 4; nn++)  // hi * hi
                        mma_bf16(acc[g * 4 + nn], ah0, ah1, ah2, ah3, bhv[nn][0], bhv[nn][1]);
#pragma unroll
                    for (int nn = 0; nn < 4; nn++)  // hi * lo
                        mma_bf16(acc[g * 4 + nn], ah0, ah1, ah2, ah3, blv[nn][0], blv[nn][1]);
#pragma unroll
                    for (int nn = 0; nn < 4; nn++)  // lo * hi
                        mma_bf16(acc[g * 4 + nn], al0, al1, al2, al3, bhv[nn][0], bhv[nn][1]);
                }
            }

            // ---- Pass epilogue 1: +csq, running minima ----
            const float* cs = smem + SCSQ(buf) + pass * 64;
            const int cbp = cbase + pass * 64;
            float tl = 3.402823466e38f, th = 3.402823466e38f;
#pragma unroll
            for (int nb = 0; nb < 8; nb++) {
                float2 c2 = *(const float2*)(cs + nb * 8 + ka * 2);
                acc[nb][0] += c2.x; acc[nb][1] += c2.y;
                acc[nb][2] += c2.x; acc[nb][3] += c2.y;
                tl = fminf(tl, fminf(acc[nb][0], acc[nb][1]));
                th = fminf(th, fminf(acc[nb][2], acc[nb][3]));
            }
            bl = fminf(bl, tl);
            bh = fminf(bh, th);
            const float thr_l = bl + DELTA, thr_h = bh + DELTA;

            // ---- Pass epilogue 2: screen into registers (NO calls here) ----
            unsigned cand[4];
            int nc = 0;
#pragma unroll
            for (int nb = 0; nb < 8; nb++) {
                const int g = cbp + nb * 8 + ka * 2;
                if (acc[nb][0] < thr_l) { if (nc < 4) cand[nc] = (unsigned)(g << 1);           nc++; }
                if (acc[nb][1] < thr_l) { if (nc < 4) cand[nc] = (unsigned)((g + 1) << 1);     nc++; }
                if (acc[nb][2] < thr_h) { if (nc < 4) cand[nc] = (unsigned)((g << 1) | 1);     nc++; }
                if (acc[nb][3] < thr_h) { if (nc < 4) cand[nc] = (unsigned)(((g + 1) << 1) | 1); nc++; }
            }

            // ---- Deferred exact rescore: acc is dead past this point ----
            if (nc > 0) {
                if (nc <= 4) {
                    for (int i = 0; i < nc; i++)
                        rescore_one(cand[i], ctx, bel, iel, beh, ieh);
                } else {
                    // Overflow (astronomically rare): rescore the full range.
                    for (int nb = 0; nb < 8; nb++) {
                        const int g = cbp + nb * 8 + ka * 2;
                        rescore_one((unsigned)(g << 1),           ctx, bel, iel, beh, ieh);
                        rescore_one((unsigned)((g + 1) << 1),     ctx, bel, iel, beh, ieh);
                        rescore_one((unsigned)((g << 1) | 1),     ctx, bel, iel, beh, ieh);
                        rescore_one((unsigned)(((g + 1) << 1) | 1), ctx, bel, iel, beh, ieh);
                    }
                }
            }
        }
        __syncthreads();

        if (tt == 31) {
            finalize_stage(0, row0, tid, w, lane, smem, cb, x, out,
                           bel, iel, beh, ieh, bl, bh);
            int c0l = ((int*)smem)[SRI + ra];
            int c0h = ((int*)smem)[SRI + ra + 8];
            qrow_l = cb + (size_t)c0l * C_DIM;
            qrow_h = cb + (size_t)c0h * C_DIM;
        }

        if (tt + 2 < 64) copy_tile(tt + 2, buf, tid, sb);
    }

    finalize_stage(1, row0, tid, w, lane, smem, rcb, x, out,
                   bel, iel, beh, ieh, bl, bh);
}

extern "C" void kernel_launch(void* const* d_in, const int* in_sizes, int n_in,
                              void* d_out, int out_size) {
    const float* x   = (const float*)d_in[0];
    const float* cb  = (const float*)d_in[1];
    const float* rcb = (const float*)d_in[2];
    float* out = (float*)d_out;

    static int smem_set = 0;
    if (!smem_set) {
        cudaFuncSetAttribute(rq8_kernel,
                             cudaFuncAttributeMaxDynamicSharedMemorySize,
                             SMEM_FLOATS * sizeof(float));
        smem_set = 1;
    }

    prep_kernel<<<K_CODES / 256, 256>>>(cb, rcb);
    rq8_kernel<<<N_ROWS / M_TILE, THREADS, SMEM_FLOATS * sizeof(float)>>>(x, cb, rcb, out);
}

// round 16
// speedup vs baseline: 3.3537x; 1.1414x over previous
#include <cuda_runtime.h>
#include <cuda_bf16.h>
#include <stdint.h>

#define N_ROWS   131072
#define C_DIM    64
#define K_CODES  4096
#define M_TILE   128
#define THREADS  256
#define DELTA    0.015625f    // screen margin >> worst-case bf16-3term error

// Output layout: [quantized N*C][idx N][residual_quantized N*C][idx_r N]
#define OFF_Q     ((size_t)0)
#define OFF_IDX   ((size_t)N_ROWS * C_DIM)
#define OFF_RQ    ((size_t)N_ROWS * C_DIM + N_ROWS)
#define OFF_IDXR  ((size_t)2 * N_ROWS * C_DIM + N_ROWS)

// GMEM images: bf16 hi/lo split of (-2*codebook), packed per 128-code tile in
// the exact SMEM fragment layout (32KB/tile) so cp.async copies are linear.
__device__ float g_imgMain[32 * 8192];
__device__ float g_imgRes [32 * 8192];
__device__ float g_csq[K_CODES];
__device__ float g_rsq[K_CODES];

// ---- SMEM float-index map ----
#define SA       0                    // A tile: 128 rows x 256B = 32KB
#define SB(b)    (8192 + (b) * 8192)  // B buffers: 32KB each
#define SCSQ(b)  (24576 + (b) * 128)
#define SRI      24832
#define SMEM_FLOATS 24992             // 99968 bytes -> 2 CTAs/SM

// Byte offset of the fragment-packed cell (r, kchunk, ka) within a tile.
// Cell = 16B: [hi(2ka..2ka+1) | hi(2ka+8..+9) | lo(2ka..) | lo(2ka+8..)].
// Parity-XOR on the 64B kc-block keeps the warp LDS.128 pattern conflict-free.
__device__ __forceinline__ int cell_byte(int r, int kc, int ka) {
    return r * 256 + ((kc ^ (r & 1)) << 6) + ka * 16;
}

__device__ __forceinline__ uint32_t bf16pair(float v0, float v1) {
    __nv_bfloat162 p = __floats2bfloat162_rn(v0, v1);
    return *(uint32_t*)&p;
}

// ---- Prep: pack bf16-split images + squared norms (one thread per code) ----
__global__ void prep_kernel(const float* __restrict__ cb,
                            const float* __restrict__ rcb) {
    int n = blockIdx.x * blockDim.x + threadIdx.x;
    if (n >= K_CODES) return;
    int t = n >> 7, r = n & 127;
#pragma unroll
    for (int img = 0; img < 2; img++) {
        const float* src = img ? rcb : cb;
        char* dst = (char*)(img ? g_imgRes : g_imgMain) + (size_t)t * 32768;
        float s = 0.f;
        for (int k = 0; k < C_DIM; k += 2) {
            float v0 = src[(size_t)n * C_DIM + k];
            float v1 = src[(size_t)n * C_DIM + k + 1];
            s = fmaf(v0, v0, fmaf(v1, v1, s));
            float w0 = -2.f * v0, w1 = -2.f * v1;
            float h0 = __bfloat162float(__float2bfloat16(w0));
            float h1 = __bfloat162float(__float2bfloat16(w1));
            int kc = k >> 4, kk = k & 15, sh = kk >> 3, ka = (kk >> 1) & 3;
            int base = cell_byte(r, kc, ka) + sh * 4;
            *(uint32_t*)(dst + base)     = bf16pair(h0, h1);
            *(uint32_t*)(dst + base + 8) = bf16pair(w0 - h0, w1 - h1);
        }
        if (img) g_rsq[n] = s; else g_csq[n] = s;
    }
}

__device__ __forceinline__ void cpasync16(uint32_t dst, const float* src) {
    asm volatile("cp.async.cg.shared.global [%0], [%1], 16;"
                 :: "r"(dst), "l"(src) : "memory");
}

__device__ __forceinline__ void mma_bf16(float* d,
                                         uint32_t a0, uint32_t a1, uint32_t a2, uint32_t a3,
                                         uint32_t b0, uint32_t b1) {
    asm volatile(
        "mma.sync.aligned.m16n8k16.row.col.f32.bf16.bf16.f32 "
        "{%0,%1,%2,%3}, {%4,%5,%6,%7}, {%8,%9}, {%0,%1,%2,%3};"
        : "+f"(d[0]), "+f"(d[1]), "+f"(d[2]), "+f"(d[3])
        : "r"(a0), "r"(a1), "r"(a2), "r"(a3), "r"(b0), "r"(b1));
}

// ---- Exact fp32 rescore core (cold path only) ----
__device__ __forceinline__ float exact_score(const float* __restrict__ xrow,
                                             const float* __restrict__ qrow,
                                             const float* __restrict__ crow,
                                             float csq)
{
    float d0 = 0.f, d1 = 0.f, d2 = 0.f, d3 = 0.f;
#pragma unroll
    for (int j = 0; j < 16; j++) {
        float4 xv = __ldg((const float4*)xrow + j);
        float4 cv = __ldg((const float4*)crow + j);
        if (qrow) {
            float4 qv = __ldg((const float4*)qrow + j);
            xv.x -= qv.x; xv.y -= qv.y; xv.z -= qv.z; xv.w -= qv.w;
        }
        d0 = fmaf(xv.x, cv.x, d0);
        d1 = fmaf(xv.y, cv.y, d1);
        d2 = fmaf(xv.z, cv.z, d2);
        d3 = fmaf(xv.w, cv.w, d3);
    }
    return fmaf(-2.f, (d0 + d1) + (d2 + d3), csq);
}

struct Best4 { float bel, beh; int iel, ieh; };

// Cold path: decode mask bits (ascending -> first-min tie-break preserved),
// exact-rescore each flagged code. Everything by value; no local-memory refs.
__device__ __noinline__ Best4 rescore_masked(
    unsigned mlo, unsigned mhi, int cbp, int ka, int row0, int ra, int stage,
    const float* __restrict__ x, const float* __restrict__ cbq,
    const float* __restrict__ cbs, const float* __restrict__ sqs,
    const int* __restrict__ sri, Best4 cur)
{
    const float* xrl = x + (size_t)(row0 + ra) * C_DIM;
    const float* xrh = xrl + 8 * C_DIM;
    const float* ql = 0;
    const float* qh = 0;
    if (stage) {
        ql = cbq + (size_t)sri[ra] * C_DIM;
        qh = cbq + (size_t)sri[ra + 8] * C_DIM;
    }
    while (mlo) {
        int b = __ffs(mlo) - 1; mlo &= mlo - 1;
        int code = cbp + (b >> 1) * 8 + ka * 2 + (b & 1);
        float e = exact_score(xrl, ql, cbs + (size_t)code * C_DIM, __ldg(sqs + code));
        if (e < cur.bel) { cur.bel = e; cur.iel = code; }
    }
    while (mhi) {
        int b = __ffs(mhi) - 1; mhi &= mhi - 1;
        int code = cbp + (b >> 1) * 8 + ka * 2 + (b & 1);
        float e = exact_score(xrh, qh, cbs + (size_t)code * C_DIM, __ldg(sqs + code));
        if (e < cur.beh) { cur.beh = e; cur.ieh = code; }
    }
    return cur;
}

// cp.async one packed code tile + csq into buffer buf.
__device__ __forceinline__ void copy_tile(int u, int buf, int tid, uint32_t sb) {
    const float* src = (u < 32 ? g_imgMain : g_imgRes) + (size_t)(u & 31) * 8192;
    uint32_t d = sb + SB(buf) * 4;
#pragma unroll
    for (int o = 0; o < 8; o++) {
        int i = tid + o * 256;
        cpasync16(d + i * 16, src + i * 4);
    }
    if (tid < 32) {
        const float* sq = (u < 32 ? g_csq : g_rsq) + (u & 31) * 128;
        cpasync16(sb + SCSQ(buf) * 4 + tid * 16, sq + tid * 4);
    }
    asm volatile("cp.async.commit_group;" ::: "memory");
}

// Build/refresh one A row (bf16 split of x or residual) into the A tile.
__device__ __forceinline__ void build_row(float* smem, int r,
                                          const float* __restrict__ xrow,
                                          const float* __restrict__ qrow) {
    char* A = (char*)smem;   // SA == 0
#pragma unroll
    for (int j = 0; j < 16; j++) {
        float4 v = ((const float4*)xrow)[j];
        if (qrow) {
            float4 q = ((const float4*)qrow)[j];
            v.x -= q.x; v.y -= q.y; v.z -= q.z; v.w -= q.w;
        }
        float va[4] = {v.x, v.y, v.z, v.w};
#pragma unroll
        for (int p = 0; p < 2; p++) {
            int k = j * 4 + p * 2;
            float w0 = va[p * 2], w1 = va[p * 2 + 1];
            float h0 = __bfloat162float(__float2bfloat16(w0));
            float h1 = __bfloat162float(__float2bfloat16(w1));
            int kc = k >> 4, kk = k & 15, sh = kk >> 3, ka = (kk >> 1) & 3;
            int base = cell_byte(r, kc, ka) + sh * 4;
            *(uint32_t*)(A + base)     = bf16pair(h0, h1);
            *(uint32_t*)(A + base + 8) = bf16pair(w0 - h0, w1 - h1);
        }
    }
}

// Stage end: quad-reduce exact argmin, gather/emit outputs, rebuild A (stage 0).
__device__ __forceinline__ void finalize_stage(
    int stage, int row0, int tid, int w, int lane,
    float* smem, const float* __restrict__ cbraw, const float* __restrict__ x,
    float* __restrict__ out,
    float& bel, int& iel, float& beh, int& ieh, float& bl, float& bh)
{
#pragma unroll
    for (int off = 1; off < 4; off <<= 1) {
        float so = __shfl_xor_sync(0xffffffffu, bel, off);
        int   bo = __shfl_xor_sync(0xffffffffu, iel, off);
        if (so < bel || (so == bel && bo < iel)) { bel = so; iel = bo; }
        so = __shfl_xor_sync(0xffffffffu, beh, off);
        bo = __shfl_xor_sync(0xffffffffu, ieh, off);
        if (so < beh || (so == beh && bo < ieh)) { beh = so; ieh = bo; }
    }
    if ((lane & 3) == 0) {
        int r = w * 16 + (lane >> 2);
        ((int*)smem)[SRI + r]     = iel;
        ((int*)smem)[SRI + r + 8] = ieh;
    }
    __syncthreads();
    if (tid < 128) {
        int r = tid;
        int code = ((int*)smem)[SRI + r];
        const float* qrow = cbraw + (size_t)code * C_DIM;
        float* oq = out + (stage ? OFF_RQ : OFF_Q) + (size_t)(row0 + r) * C_DIM;
#pragma unroll
        for (int j = 0; j < 16; j++)
            *(float4*)(oq + j * 4) = ((const float4*)qrow)[j];
        if (stage == 0)
            build_row(smem, r, x + (size_t)(row0 + r) * C_DIM, qrow);
        out[(stage ? OFF_IDXR : OFF_IDX) + row0 + r] = (float)code;
    }
    bel = beh = 3.402823466e38f; iel = ieh = 0;
    bl  = bh  = 3.402823466e38f;
    __syncthreads();
}

__global__ __launch_bounds__(THREADS, 2)
void rq9_kernel(const float* __restrict__ x,
                const float* __restrict__ cb,
                const float* __restrict__ rcb,
                float* __restrict__ out)
{
    extern __shared__ float smem[];
    const uint32_t sb = (uint32_t)__cvta_generic_to_shared(smem);
    const int tid = threadIdx.x, w = tid >> 5, lane = tid & 31;
    const int row0 = blockIdx.x * M_TILE;

    copy_tile(0, 0, tid, sb);
    copy_tile(1, 1, tid, sb);

    if (tid < 128)
        build_row(smem, tid, x + (size_t)(row0 + tid) * C_DIM, (const float*)0);

    float bl = 3.402823466e38f, bh = 3.402823466e38f;     // approx screens
    float bel = 3.402823466e38f, beh = 3.402823466e38f;   // exact bests
    int   iel = 0, ieh = 0;

    const int ra = w * 16 + (lane >> 2);
    const int ka = lane & 3;
    const int q  = lane >> 2;
    const int abase = ra * 256 + ka * 16;   // A cell base (ra, ra+8 same parity)
    const int apar  = ra & 1;
    const int bblk  = q * 256 + ka * 16;    // B cell base within an n-block
    const int bpar  = q & 1;

    for (int tt = 0; tt < 64; tt++) {
        if (tt < 63) asm volatile("cp.async.wait_group 1;" ::: "memory");
        else         asm volatile("cp.async.wait_group 0;" ::: "memory");
        __syncthreads();

        const int buf = tt & 1;
        const int stage = tt >> 5;
        const char* A = (const char*)smem;
        const char* B = (const char*)smem + SB(buf) * 4;
        const int cbase = (tt & 31) * 128;

#pragma unroll
        for (int pass = 0; pass < 2; pass++) {
            const char* Bp = B + pass * 16384;      // n-blocks 8..15 at +16KB

            float acc[8][4];
#pragma unroll
            for (int nb = 0; nb < 8; nb++)
#pragma unroll
                for (int j = 0; j < 4; j++) acc[nb][j] = 0.f;

#pragma unroll
            for (int kc = 0; kc < 4; kc++) {
                const int ablk = ((kc ^ apar) << 6);
                float4 fa = *(const float4*)(A + abase + ablk);
                float4 fb = *(const float4*)(A + abase + 2048 + ablk);
                uint32_t ah0 = __float_as_uint(fa.x), ah2 = __float_as_uint(fa.y);
                uint32_t al0 = __float_as_uint(fa.z), al2 = __float_as_uint(fa.w);
                uint32_t ah1 = __float_as_uint(fb.x), ah3 = __float_as_uint(fb.y);
                uint32_t al1 = __float_as_uint(fb.z), al3 = __float_as_uint(fb.w);
                const char* Bk = Bp + bblk + ((kc ^ bpar) << 6);
#pragma unroll
                for (int g = 0; g < 2; g++) {       // 2 groups of 4 n-blocks
                    uint32_t bhv[4][2], blv[4][2];
#pragma unroll
                    for (int nn = 0; nn < 4; nn++) {
                        float4 f = *(const float4*)(Bk + (g * 4 + nn) * 2048);
                        bhv[nn][0] = __float_as_uint(f.x); bhv[nn][1] = __float_as_uint(f.y);
                        blv[nn][0] = __float_as_uint(f.z); blv[nn][1] = __float_as_uint(f.w);
                    }
#pragma unroll
                    for (int nn = 0; nn < 4; nn++)  // hi * hi
                        mma_bf16(acc[g * 4 + nn], ah0, ah1, ah2, ah3, bhv[nn][0], bhv[nn][1]);
#pragma unroll
                    for (int nn = 0; nn < 4; nn++)  // hi * lo
                        mma_bf16(acc[g * 4 + nn], ah0, ah1, ah2, ah3, blv[nn][0], blv[nn][1]);
#pragma unroll
                    for (int nn = 0; nn < 4; nn++)  // lo * hi
                        mma_bf16(acc[g * 4 + nn], al0, al1, al2, al3, bhv[nn][0], bhv[nn][1]);
                }
            }

            // ---- Pass epilogue 1: +csq, running minima ----
            const float* cs = smem + SCSQ(buf) + pass * 64;
            const int cbp = cbase + pass * 64;
            float tl = 3.402823466e38f, th = 3.402823466e38f;
#pragma unroll
            for (int nb = 0; nb < 8; nb++) {
                float2 c2 = *(const float2*)(cs + nb * 8 + ka * 2);
                acc[nb][0] += c2.x; acc[nb][1] += c2.y;
                acc[nb][2] += c2.x; acc[nb][3] += c2.y;
                tl = fminf(tl, fminf(acc[nb][0], acc[nb][1]));
                th = fminf(th, fminf(acc[nb][2], acc[nb][3]));
            }
            bl = fminf(bl, tl);
            bh = fminf(bh, th);
            const float thr_l = bl + DELTA, thr_h = bh + DELTA;

            // ---- Pass epilogue 2: branch-free bitmask screen ----
            unsigned mlo = 0, mhi = 0;
#pragma unroll
            for (int nb = 0; nb < 8; nb++) {
                if (acc[nb][0] < thr_l) mlo |= 1u << (2 * nb);
                if (acc[nb][1] < thr_l) mlo |= 1u << (2 * nb + 1);
                if (acc[nb][2] < thr_h) mhi |= 1u << (2 * nb);
                if (acc[nb][3] < thr_h) mhi |= 1u << (2 * nb + 1);
            }

            // ---- Cold path: exact rescore of flagged codes (acc dead) ----
            if (mlo | mhi) {
                Best4 cur; cur.bel = bel; cur.beh = beh; cur.iel = iel; cur.ieh = ieh;
                cur = rescore_masked(mlo, mhi, cbp, ka, row0, ra, stage,
                                     x, cb, stage ? rcb : cb,
                                     stage ? g_rsq : g_csq,
                                     (const int*)smem + SRI, cur);
                bel = cur.bel; beh = cur.beh; iel = cur.iel; ieh = cur.ieh;
            }
        }
        __syncthreads();

        if (tt == 31)
            finalize_stage(0, row0, tid, w, lane, smem, cb, x, out,
                           bel, iel, beh, ieh, bl, bh);

        if (tt + 2 < 64) copy_tile(tt + 2, buf, tid, sb);
    }

    finalize_stage(1, row0, tid, w, lane, smem, rcb, x, out,
                   bel, iel, beh, ieh, bl, bh);
}

extern "C" void kernel_launch(void* const* d_in, const int* in_sizes, int n_in,
                              void* d_out, int out_size) {
    const float* x   = (const float*)d_in[0];
    const float* cb  = (const float*)d_in[1];
    const float* rcb = (const float*)d_in[2];
    float* out = (float*)d_out;

    static int smem_set = 0;
    if (!smem_set) {
        cudaFuncSetAttribute(rq9_kernel,
                             cudaFuncAttributeMaxDynamicSharedMemorySize,
                             SMEM_FLOATS * sizeof(float));
        smem_set = 1;
    }

    prep_kernel<<<K_CODES / 256, 256>>>(cb, rcb);
    rq9_kernel<<<N_ROWS / M_TILE, THREADS, SMEM_FLOATS * sizeof(float)>>>(x, cb, rcb, out);
}

// round 17
// speedup vs baseline: 3.5343x; 1.0539x over previous
#include <cuda_runtime.h>
#include <cuda_bf16.h>
#include <stdint.h>

#define N_ROWS   131072
#define C_DIM    64
#define K_CODES  4096
#define M_TILE   128
#define THREADS  256
#define DELTA    0.015625f    // screen margin >> worst-case bf16-3term error

// Output layout: [quantized N*C][idx N][residual_quantized N*C][idx_r N]
#define OFF_Q     ((size_t)0)
#define OFF_IDX   ((size_t)N_ROWS * C_DIM)
#define OFF_RQ    ((size_t)N_ROWS * C_DIM + N_ROWS)
#define OFF_IDXR  ((size_t)2 * N_ROWS * C_DIM + N_ROWS)

// GMEM images: bf16 hi/lo split of (-2*codebook), packed per 128-code tile in
// the exact SMEM fragment layout (32KB/tile) so cp.async copies are linear.
__device__ float g_imgMain[32 * 8192];
__device__ float g_imgRes [32 * 8192];
__device__ float g_csq[K_CODES];
__device__ float g_rsq[K_CODES];

// ---- SMEM float-index map ----
#define SA       0                    // A tile: 128 rows x 256B = 32KB
#define SB(b)    (8192 + (b) * 8192)  // B buffers: 32KB each
#define SCSQ(b)  (24576 + (b) * 128)
#define SRI      24832
#define SMEM_FLOATS 24992             // 99968 bytes -> 2 CTAs/SM

// Byte offset of the fragment-packed cell (r, kchunk, ka) within a tile.
// Cell = 16B: [hi(2ka..2ka+1) | hi(2ka+8..+9) | lo(2ka..) | lo(2ka+8..)].
// Parity-XOR on the 64B kc-block keeps the warp LDS.128 pattern conflict-free.
__device__ __forceinline__ int cell_byte(int r, int kc, int ka) {
    return r * 256 + ((kc ^ (r & 1)) << 6) + ka * 16;
}

__device__ __forceinline__ uint32_t bf16pair(float v0, float v1) {
    __nv_bfloat162 p = __floats2bfloat162_rn(v0, v1);
    return *(uint32_t*)&p;
}

// ---- Prep: pack bf16-split images + squared norms (one thread per code) ----
__global__ void prep_kernel(const float* __restrict__ cb,
                            const float* __restrict__ rcb) {
    int n = blockIdx.x * blockDim.x + threadIdx.x;
    if (n >= K_CODES) return;
    int t = n >> 7, r = n & 127;
#pragma unroll
    for (int img = 0; img < 2; img++) {
        const float* src = img ? rcb : cb;
        char* dst = (char*)(img ? g_imgRes : g_imgMain) + (size_t)t * 32768;
        float s = 0.f;
        for (int k = 0; k < C_DIM; k += 2) {
            float v0 = src[(size_t)n * C_DIM + k];
            float v1 = src[(size_t)n * C_DIM + k + 1];
            s = fmaf(v0, v0, fmaf(v1, v1, s));
            float w0 = -2.f * v0, w1 = -2.f * v1;
            float h0 = __bfloat162float(__float2bfloat16(w0));
            float h1 = __bfloat162float(__float2bfloat16(w1));
            int kc = k >> 4, kk = k & 15, sh = kk >> 3, ka = (kk >> 1) & 3;
            int base = cell_byte(r, kc, ka) + sh * 4;
            *(uint32_t*)(dst + base)     = bf16pair(h0, h1);
            *(uint32_t*)(dst + base + 8) = bf16pair(w0 - h0, w1 - h1);
        }
        if (img) g_rsq[n] = s; else g_csq[n] = s;
    }
}

__device__ __forceinline__ void cpasync16(uint32_t dst, const float* src) {
    asm volatile("cp.async.cg.shared.global [%0], [%1], 16;"
                 :: "r"(dst), "l"(src) : "memory");
}

__device__ __forceinline__ void mma_bf16(float* d,
                                         uint32_t a0, uint32_t a1, uint32_t a2, uint32_t a3,
                                         uint32_t b0, uint32_t b1) {
    asm volatile(
        "mma.sync.aligned.m16n8k16.row.col.f32.bf16.bf16.f32 "
        "{%0,%1,%2,%3}, {%4,%5,%6,%7}, {%8,%9}, {%0,%1,%2,%3};"
        : "+f"(d[0]), "+f"(d[1]), "+f"(d[2]), "+f"(d[3])
        : "r"(a0), "r"(a1), "r"(a2), "r"(a3), "r"(b0), "r"(b1));
}

// ---- Exact fp32 rescore core (cold path only) ----
__device__ __forceinline__ float exact_score(const float* __restrict__ xrow,
                                             const float* __restrict__ qrow,
                                             const float* __restrict__ crow,
                                             float csq)
{
    float d0 = 0.f, d1 = 0.f, d2 = 0.f, d3 = 0.f;
#pragma unroll
    for (int j = 0; j < 16; j++) {
        float4 xv = __ldg((const float4*)xrow + j);
        float4 cv = __ldg((const float4*)crow + j);
        if (qrow) {
            float4 qv = __ldg((const float4*)qrow + j);
            xv.x -= qv.x; xv.y -= qv.y; xv.z -= qv.z; xv.w -= qv.w;
        }
        d0 = fmaf(xv.x, cv.x, d0);
        d1 = fmaf(xv.y, cv.y, d1);
        d2 = fmaf(xv.z, cv.z, d2);
        d3 = fmaf(xv.w, cv.w, d3);
    }
    return fmaf(-2.f, (d0 + d1) + (d2 + d3), csq);
}

struct Best4 { float bel, beh; int iel, ieh; };

// Cold path: decode mask bits (ascending -> first-min tie-break preserved),
// exact-rescore each flagged code. Everything by value; no local-memory refs.
__device__ __noinline__ Best4 rescore_masked(
    unsigned mlo, unsigned mhi, int cbp, int ka, int row0, int ra, int stage,
    const float* __restrict__ x, const float* __restrict__ cbq,
    const float* __restrict__ cbs, const float* __restrict__ sqs,
    const int* __restrict__ sri, Best4 cur)
{
    const float* xrl = x + (size_t)(row0 + ra) * C_DIM;
    const float* xrh = xrl + 8 * C_DIM;
    const float* ql = 0;
    const float* qh = 0;
    if (stage) {
        ql = cbq + (size_t)sri[ra] * C_DIM;
        qh = cbq + (size_t)sri[ra + 8] * C_DIM;
    }
    while (mlo) {
        int b = __ffs(mlo) - 1; mlo &= mlo - 1;
        int code = cbp + (b >> 1) * 8 + ka * 2 + (b & 1);
        float e = exact_score(xrl, ql, cbs + (size_t)code * C_DIM, __ldg(sqs + code));
        if (e < cur.bel) { cur.bel = e; cur.iel = code; }
    }
    while (mhi) {
        int b = __ffs(mhi) - 1; mhi &= mhi - 1;
        int code = cbp + (b >> 1) * 8 + ka * 2 + (b & 1);
        float e = exact_score(xrh, qh, cbs + (size_t)code * C_DIM, __ldg(sqs + code));
        if (e < cur.beh) { cur.beh = e; cur.ieh = code; }
    }
    return cur;
}

// cp.async one packed code tile + csq into buffer buf.
__device__ __forceinline__ void copy_tile(int u, int buf, int tid, uint32_t sb) {
    const float* src = (u < 32 ? g_imgMain : g_imgRes) + (size_t)(u & 31) * 8192;
    uint32_t d = sb + SB(buf) * 4;
#pragma unroll
    for (int o = 0; o < 8; o++) {
        int i = tid + o * 256;
        cpasync16(d + i * 16, src + i * 4);
    }
    if (tid < 32) {
        const float* sq = (u < 32 ? g_csq : g_rsq) + (u & 31) * 128;
        cpasync16(sb + SCSQ(buf) * 4 + tid * 16, sq + tid * 4);
    }
    asm volatile("cp.async.commit_group;" ::: "memory");
}

// Build/refresh one A row (bf16 split of x or residual) into the A tile.
__device__ __forceinline__ void build_row(float* smem, int r,
                                          const float* __restrict__ xrow,
                                          const float* __restrict__ qrow) {
    char* A = (char*)smem;   // SA == 0
#pragma unroll
    for (int j = 0; j < 16; j++) {
        float4 v = ((const float4*)xrow)[j];
        if (qrow) {
            float4 q = ((const float4*)qrow)[j];
            v.x -= q.x; v.y -= q.y; v.z -= q.z; v.w -= q.w;
        }
        float va[4] = {v.x, v.y, v.z, v.w};
#pragma unroll
        for (int p = 0; p < 2; p++) {
            int k = j * 4 + p * 2;
            float w0 = va[p * 2], w1 = va[p * 2 + 1];
            float h0 = __bfloat162float(__float2bfloat16(w0));
            float h1 = __bfloat162float(__float2bfloat16(w1));
            int kc = k >> 4, kk = k & 15, sh = kk >> 3, ka = (kk >> 1) & 3;
            int base = cell_byte(r, kc, ka) + sh * 4;
            *(uint32_t*)(A + base)     = bf16pair(h0, h1);
            *(uint32_t*)(A + base + 8) = bf16pair(w0 - h0, w1 - h1);
        }
    }
}

// Stage end: quad-reduce exact argmin, gather/emit outputs, rebuild A (stage 0).
__device__ __forceinline__ void finalize_stage(
    int stage, int row0, int tid, int w, int lane,
    float* smem, const float* __restrict__ cbraw, const float* __restrict__ x,
    float* __restrict__ out,
    float& bel, int& iel, float& beh, int& ieh, float& bl, float& bh)
{
#pragma unroll
    for (int off = 1; off < 4; off <<= 1) {
        float so = __shfl_xor_sync(0xffffffffu, bel, off);
        int   bo = __shfl_xor_sync(0xffffffffu, iel, off);
        if (so < bel || (so == bel && bo < iel)) { bel = so; iel = bo; }
        so = __shfl_xor_sync(0xffffffffu, beh, off);
        bo = __shfl_xor_sync(0xffffffffu, ieh, off);
        if (so < beh || (so == beh && bo < ieh)) { beh = so; ieh = bo; }
    }
    if ((lane & 3) == 0) {
        int r = w * 16 + (lane >> 2);
        ((int*)smem)[SRI + r]     = iel;
        ((int*)smem)[SRI + r + 8] = ieh;
    }
    __syncthreads();
    if (tid < 128) {
        int r = tid;
        int code = ((int*)smem)[SRI + r];
        const float* qrow = cbraw + (size_t)code * C_DIM;
        float* oq = out + (stage ? OFF_RQ : OFF_Q) + (size_t)(row0 + r) * C_DIM;
#pragma unroll
        for (int j = 0; j < 16; j++)
            *(float4*)(oq + j * 4) = ((const float4*)qrow)[j];
        if (stage == 0)
            build_row(smem, r, x + (size_t)(row0 + r) * C_DIM, qrow);
        out[(stage ? OFF_IDXR : OFF_IDX) + row0 + r] = (float)code;
    }
    bel = beh = 3.402823466e38f; iel = ieh = 0;
    bl  = bh  = 3.402823466e38f;
    __syncthreads();
}

__global__ __launch_bounds__(THREADS, 2)
void rq10_kernel(const float* __restrict__ x,
                 const float* __restrict__ cb,
                 const float* __restrict__ rcb,
                 float* __restrict__ out)
{
    extern __shared__ float smem[];
    const uint32_t sb = (uint32_t)__cvta_generic_to_shared(smem);
    const int tid = threadIdx.x, w = tid >> 5, lane = tid & 31;
    const int row0 = blockIdx.x * M_TILE;

    copy_tile(0, 0, tid, sb);
    copy_tile(1, 1, tid, sb);

    if (tid < 128)
        build_row(smem, tid, x + (size_t)(row0 + tid) * C_DIM, (const float*)0);
    __syncthreads();

    float bl = 3.402823466e38f, bh = 3.402823466e38f;     // approx screens
    float bel = 3.402823466e38f, beh = 3.402823466e38f;   // exact bests
    int   iel = 0, ieh = 0;

    const int ra = w * 16 + (lane >> 2);
    const int ka = lane & 3;
    const int q  = lane >> 2;
    const int abase = ra * 256 + ka * 16;   // A cell base (ra, ra+8 same parity)
    const int apar  = ra & 1;
    const int bblk  = q * 256 + ka * 16;    // B cell base within an n-block
    const int bpar  = q & 1;

    // ---- A fragments hoisted to registers: constant for a whole stage ----
    uint32_t Ah[4][4], Al[4][4];
#define LOAD_A_FRAGS()                                                        \
    {                                                                         \
        const char* A_ = (const char*)smem;                                   \
        _Pragma("unroll")                                                     \
        for (int kc = 0; kc < 4; kc++) {                                      \
            const int ablk = ((kc ^ apar) << 6);                              \
            float4 fa = *(const float4*)(A_ + abase + ablk);                  \
            float4 fb = *(const float4*)(A_ + abase + 2048 + ablk);           \
            Ah[kc][0] = __float_as_uint(fa.x); Ah[kc][2] = __float_as_uint(fa.y); \
            Al[kc][0] = __float_as_uint(fa.z); Al[kc][2] = __float_as_uint(fa.w); \
            Ah[kc][1] = __float_as_uint(fb.x); Ah[kc][3] = __float_as_uint(fb.y); \
            Al[kc][1] = __float_as_uint(fb.z); Al[kc][3] = __float_as_uint(fb.w); \
        }                                                                     \
    }
    LOAD_A_FRAGS();

    for (int tt = 0; tt < 64; tt++) {
        if (tt < 63) asm volatile("cp.async.wait_group 1;" ::: "memory");
        else         asm volatile("cp.async.wait_group 0;" ::: "memory");
        __syncthreads();

        const int buf = tt & 1;
        const int stage = tt >> 5;
        const char* B = (const char*)smem + SB(buf) * 4;
        const int cbase = (tt & 31) * 128;

#pragma unroll
        for (int pass = 0; pass < 2; pass++) {
            const char* Bp = B + bblk + pass * 16384;  // n-blocks 8..15 at +16KB

            float acc[8][4];
#pragma unroll
            for (int nb = 0; nb < 8; nb++)
#pragma unroll
                for (int j = 0; j < 4; j++) acc[nb][j] = 0.f;

            // Software-pipelined B groups: it = kc*2 + g, double-buffered regs.
            float4 fcur[4], fnxt[4];
            {
                const char* Bk = Bp + ((0 ^ bpar) << 6);
#pragma unroll
                for (int nn = 0; nn < 4; nn++)
                    fcur[nn] = *(const float4*)(Bk + nn * 2048);
            }
#pragma unroll
            for (int it = 0; it < 8; it++) {
                const int kc = it >> 1, g = it & 1;
                if (it < 7) {
                    const int kc2 = (it + 1) >> 1, g2 = (it + 1) & 1;
                    const char* Bk = Bp + ((kc2 ^ bpar) << 6);
#pragma unroll
                    for (int nn = 0; nn < 4; nn++)
                        fnxt[nn] = *(const float4*)(Bk + (g2 * 4 + nn) * 2048);
                }
                uint32_t bhv[4][2], blv[4][2];
#pragma unroll
                for (int nn = 0; nn < 4; nn++) {
                    bhv[nn][0] = __float_as_uint(fcur[nn].x);
                    bhv[nn][1] = __float_as_uint(fcur[nn].y);
                    blv[nn][0] = __float_as_uint(fcur[nn].z);
                    blv[nn][1] = __float_as_uint(fcur[nn].w);
                }
#pragma unroll
                for (int nn = 0; nn < 4; nn++)  // hi * hi
                    mma_bf16(acc[g * 4 + nn], Ah[kc][0], Ah[kc][1], Ah[kc][2], Ah[kc][3],
                             bhv[nn][0], bhv[nn][1]);
#pragma unroll
                for (int nn = 0; nn < 4; nn++)  // hi * lo
                    mma_bf16(acc[g * 4 + nn], Ah[kc][0], Ah[kc][1], Ah[kc][2], Ah[kc][3],
                             blv[nn][0], blv[nn][1]);
#pragma unroll
                for (int nn = 0; nn < 4; nn++)  // lo * hi
                    mma_bf16(acc[g * 4 + nn], Al[kc][0], Al[kc][1], Al[kc][2], Al[kc][3],
                             bhv[nn][0], bhv[nn][1]);
#pragma unroll
                for (int nn = 0; nn < 4; nn++) fcur[nn] = fnxt[nn];
            }

            // ---- Pass epilogue 1: +csq, running minima ----
            const float* cs = smem + SCSQ(buf) + pass * 64;
            const int cbp = cbase + pass * 64;
            float tl = 3.402823466e38f, th = 3.402823466e38f;
#pragma unroll
            for (int nb = 0; nb < 8; nb++) {
                float2 c2 = *(const float2*)(cs + nb * 8 + ka * 2);
                acc[nb][0] += c2.x; acc[nb][1] += c2.y;
                acc[nb][2] += c2.x; acc[nb][3] += c2.y;
                tl = fminf(tl, fminf(acc[nb][0], acc[nb][1]));
                th = fminf(th, fminf(acc[nb][2], acc[nb][3]));
            }
            bl = fminf(bl, tl);
            bh = fminf(bh, th);
            const float thr_l = bl + DELTA, thr_h = bh + DELTA;

            // ---- Pass epilogue 2: branch-free bitmask screen ----
            unsigned mlo = 0, mhi = 0;
#pragma unroll
            for (int nb = 0; nb < 8; nb++) {
                if (acc[nb][0] < thr_l) mlo |= 1u << (2 * nb);
                if (acc[nb][1] < thr_l) mlo |= 1u << (2 * nb + 1);
                if (acc[nb][2] < thr_h) mhi |= 1u << (2 * nb);
                if (acc[nb][3] < thr_h) mhi |= 1u << (2 * nb + 1);
            }

            // ---- Cold path: exact rescore of flagged codes (acc dead) ----
            if (mlo | mhi) {
                Best4 cur; cur.bel = bel; cur.beh = beh; cur.iel = iel; cur.ieh = ieh;
                cur = rescore_masked(mlo, mhi, cbp, ka, row0, ra, stage,
                                     x, cb, stage ? rcb : cb,
                                     stage ? g_rsq : g_csq,
                                     (const int*)smem + SRI, cur);
                bel = cur.bel; beh = cur.beh; iel = cur.iel; ieh = cur.ieh;
            }
        }
        __syncthreads();

        if (tt == 31) {
            finalize_stage(0, row0, tid, w, lane, smem, cb, x, out,
                           bel, iel, beh, ieh, bl, bh);
            LOAD_A_FRAGS();   // A tile now holds residuals
        }

        if (tt + 2 < 64) copy_tile(tt + 2, buf, tid, sb);
    }

    finalize_stage(1, row0, tid, w, lane, smem, rcb, x, out,
                   bel, iel, beh, ieh, bl, bh);
}

extern "C" void kernel_launch(void* const* d_in, const int* in_sizes, int n_in,
                              void* d_out, int out_size) {
    const float* x   = (const float*)d_in[0];
    const float* cb  = (const float*)d_in[1];
    const float* rcb = (const float*)d_in[2];
    float* out = (float*)d_out;

    static int smem_set = 0;
    if (!smem_set) {
        cudaFuncSetAttribute(rq10_kernel,
                             cudaFuncAttributeMaxDynamicSharedMemorySize,
                             SMEM_FLOATS * sizeof(float));
        smem_set = 1;
    }

    prep_kernel<<<K_CODES / 256, 256>>>(cb, rcb);
    rq10_kernel<<<N_ROWS / M_TILE, THREADS, SMEM_FLOATS * sizeof(float)>>>(x, cb, rcb, out);
}